// round 2
// baseline (speedup 1.0000x reference)
#include <cuda_runtime.h>
#include <cstddef>

#define B_   4096
#define T_   50
#define IN_  4
#define H_   256
#define G4_  1024
#define G8_  2048          // dup-pair row width: 256 hu * 4 gates * 2 dup
#define K_   3
#define FS_  6
#define ROWS 32
#define ST   36            // padded smem row stride (floats)
#define NTHREADS 1024
#define NCTA (B_ / ROWS)   // 128

typedef unsigned long long ull;

// ---------------- device scratch (no allocs allowed) ----------------
// Dup-interleaved transposed weights: WT[j][hu*8 + gate*2 + {0,1}] = W[gate*H+hu][j]
// so one LDG.128 yields two ready FFMA2 B-operands (w,w). +G8_ pad for prefetch.
__device__ float g_WT_ih0[(IN_ + 1) * G8_];
__device__ float g_WT_hh0[(H_ + 1) * G8_];
__device__ float g_WT_cat1[(2 * H_ + 1) * G8_];      // [Wih1 ; Whh1]
__device__ float g_B0[G4_];
__device__ float g_B1[G4_];
__device__ float g_dWT_ih0[K_][(2 + 1) * G8_];
__device__ float g_dWT_hh0[K_][(H_ + 1) * G8_];
__device__ float g_dWT_cat1[K_][(2 * H_ + 1) * G8_];
__device__ float g_dB0[K_][G4_];
__device__ float g_dB1[K_][G4_];
// encoder-final state checkpoint, layout [hu*B_ + b]
__device__ float g_h0e[H_ * B_];
__device__ float g_h1e[H_ * B_];
__device__ float g_c0e[H_ * B_];
__device__ float g_c1e[H_ * B_];

// ---------------- packed fp32x2 helpers ----------------
__device__ __forceinline__ void fma2(ull& acc, ull a, ull b) {
    asm("fma.rn.f32x2 %0, %1, %2, %0;" : "+l"(acc) : "l"(a), "l"(b));
}
__device__ __forceinline__ ull pack2(float x, float y) {
    ull u;
    asm("mov.b64 %0, {%1, %2};" : "=l"(u) : "f"(x), "f"(y));
    return u;
}
__device__ __forceinline__ float2 unpack2(ull u) {
    float2 v;
    asm("mov.b64 {%0, %1}, %2;" : "=f"(v.x), "=f"(v.y) : "l"(u));
    return v;
}
__device__ __forceinline__ float sigf(float x)  { return 1.f / (1.f + __expf(-x)); }
__device__ __forceinline__ float tanhx(float x) { return 2.f / (1.f + __expf(-2.f * x)) - 1.f; }

// ---------------- prep: transpose + gate-interleave + duplicate ----------------
__global__ void prep_kernel(
    const float* __restrict__ eWih0, const float* __restrict__ eWhh0,
    const float* __restrict__ ebih0, const float* __restrict__ ebhh0,
    const float* __restrict__ eWih1, const float* __restrict__ eWhh1,
    const float* __restrict__ ebih1, const float* __restrict__ ebhh1,
    const float* __restrict__ dWih0, const float* __restrict__ dWhh0,
    const float* __restrict__ dbih0, const float* __restrict__ dbhh0,
    const float* __restrict__ dWih1, const float* __restrict__ dWhh1,
    const float* __restrict__ dbih1, const float* __restrict__ dbhh1)
{
    const int N0 = IN_ * G8_;
    const int N1 = H_ * G8_;
    const int N2 = 2 * H_ * G8_;
    const int N3 = G4_, N4 = G4_;
    const int N5 = K_ * 2 * G8_;
    const int N6 = K_ * H_ * G8_;
    const int N7 = K_ * 2 * H_ * G8_;
    const int N8 = K_ * G4_, N9 = K_ * G4_;
    const int TOT = N0 + N1 + N2 + N3 + N4 + N5 + N6 + N7 + N8 + N9;
    for (int idx = blockIdx.x * blockDim.x + threadIdx.x; idx < TOT;
         idx += gridDim.x * blockDim.x) {
        int i = idx;
        if (i < N0) { int j = i / G8_; int rem = i - j * G8_; int hu = rem >> 3, g = (rem >> 1) & 3;
            g_WT_ih0[i] = eWih0[(g * H_ + hu) * IN_ + j]; continue; }
        i -= N0;
        if (i < N1) { int j = i / G8_; int rem = i - j * G8_; int hu = rem >> 3, g = (rem >> 1) & 3;
            g_WT_hh0[i] = eWhh0[(g * H_ + hu) * H_ + j]; continue; }
        i -= N1;
        if (i < N2) { int j = i / G8_; int rem = i - j * G8_; int hu = rem >> 3, g = (rem >> 1) & 3;
            g_WT_cat1[i] = (j < H_) ? eWih1[(g * H_ + hu) * H_ + j]
                                    : eWhh1[(g * H_ + hu) * H_ + (j - H_)]; continue; }
        i -= N2;
        if (i < N3) { int hu = i >> 2, g = i & 3;
            g_B0[i] = ebih0[g * H_ + hu] + ebhh0[g * H_ + hu]; continue; }
        i -= N3;
        if (i < N4) { int hu = i >> 2, g = i & 3;
            g_B1[i] = ebih1[g * H_ + hu] + ebhh1[g * H_ + hu]; continue; }
        i -= N4;
        if (i < N5) { int k = i / (2 * G8_); int rem2 = i - k * 2 * G8_;
            int j = rem2 / G8_; int rem = rem2 - j * G8_; int hu = rem >> 3, g = (rem >> 1) & 3;
            g_dWT_ih0[k][rem2] = dWih0[(k * G4_ + g * H_ + hu) * 2 + j]; continue; }
        i -= N5;
        if (i < N6) { int k = i / (H_ * G8_); int rem2 = i - k * H_ * G8_;
            int j = rem2 / G8_; int rem = rem2 - j * G8_; int hu = rem >> 3, g = (rem >> 1) & 3;
            g_dWT_hh0[k][rem2] = dWhh0[(k * G4_ + g * H_ + hu) * H_ + j]; continue; }
        i -= N6;
        if (i < N7) { int k = i / (2 * H_ * G8_); int rem2 = i - k * 2 * H_ * G8_;
            int j = rem2 / G8_; int rem = rem2 - j * G8_; int hu = rem >> 3, g = (rem >> 1) & 3;
            g_dWT_cat1[k][rem2] = (j < H_) ? dWih1[(k * G4_ + g * H_ + hu) * H_ + j]
                                           : dWhh1[(k * G4_ + g * H_ + hu) * H_ + (j - H_)]; continue; }
        i -= N7;
        if (i < N8) { int k = i / G4_; int rem = i - k * G4_; int hu = rem >> 2, g = rem & 3;
            g_dB0[k][rem] = dbih0[k * G4_ + g * H_ + hu] + dbhh0[k * G4_ + g * H_ + hu]; continue; }
        i -= N8;
        { int k = i / G4_; int rem = i - k * G4_; int hu = rem >> 2, g = rem & 3;
            g_dB1[k][rem] = dbih1[k * G4_ + g * H_ + hu] + dbhh1[k * G4_ + g * H_ + hu]; }
    }
}

// ---------------- hot-loop macros ----------------
// acc[p][g] : f32x2 accumulator for row pair (r0+2p, r0+2p+1), gate g (i,f,g,o)
#define ACC_INIT(BIAS) {                                                        \
    _Pragma("unroll")                                                           \
    for (int g_ = 0; g_ < 4; ++g_) {                                            \
        float bv_ = (BIAS)[u4 + g_];                                            \
        ull bp_ = pack2(bv_, bv_);                                              \
        acc[0][g_] = bp_; acc[1][g_] = bp_; acc[2][g_] = bp_; acc[3][g_] = bp_; \
    } }

// weights pre-duplicated: 2x LDG.128 per j gives (wi,wi)(wf,wf)(wg,wg)(wo,wo)
// explicit prefetch of j+1 (arrays padded by one G8_ row)
#define GATE_SEG(SRC, NJ, WT) {                                                 \
    const float* __restrict__ wt_ = (WT);                                       \
    const float* __restrict__ sr_ = (SRC) + r0;                                 \
    ulonglong2 wA_ = *(const ulonglong2*)(wt_ + u8);                            \
    ulonglong2 wB_ = *(const ulonglong2*)(wt_ + u8 + 4);                        \
    _Pragma("unroll 2")                                                         \
    for (int j = 0; j < (NJ); ++j) {                                            \
        const ull* hp_ = (const ull*)(sr_ + j * ST);                            \
        ull h01 = hp_[0], h23 = hp_[1], h45 = hp_[2], h67 = hp_[3];             \
        ull wi_ = wA_.x, wf_ = wA_.y, wg_ = wB_.x, wo_ = wB_.y;                 \
        const float* nx_ = wt_ + (j + 1) * G8_ + u8;                            \
        wA_ = *(const ulonglong2*)(nx_);                                        \
        wB_ = *(const ulonglong2*)(nx_ + 4);                                    \
        fma2(acc[0][0], h01, wi_); fma2(acc[1][0], h23, wi_); fma2(acc[2][0], h45, wi_); fma2(acc[3][0], h67, wi_); \
        fma2(acc[0][1], h01, wf_); fma2(acc[1][1], h23, wf_); fma2(acc[2][1], h45, wf_); fma2(acc[3][1], h67, wf_); \
        fma2(acc[0][2], h01, wg_); fma2(acc[1][2], h23, wg_); fma2(acc[2][2], h45, wg_); fma2(acc[3][2], h67, wg_); \
        fma2(acc[0][3], h01, wo_); fma2(acc[1][3], h23, wo_); fma2(acc[2][3], h45, wo_); fma2(acc[3][3], h67, wo_); \
    } }

#define ELEMWISE(CS, HS) {                                                      \
    float cb_[8], hb_[8];                                                       \
    *(float4*)&cb_[0] = *(const float4*)&(CS)[srow];                            \
    *(float4*)&cb_[4] = *(const float4*)&(CS)[srow + 4];                        \
    _Pragma("unroll")                                                           \
    for (int p_ = 0; p_ < 4; ++p_) {                                            \
        float2 gi_ = unpack2(acc[p_][0]);                                       \
        float2 gf_ = unpack2(acc[p_][1]);                                       \
        float2 gg_ = unpack2(acc[p_][2]);                                       \
        float2 go_ = unpack2(acc[p_][3]);                                       \
        float c0v_ = sigf(gf_.x) * cb_[2 * p_]     + sigf(gi_.x) * tanhx(gg_.x);\
        float c1v_ = sigf(gf_.y) * cb_[2 * p_ + 1] + sigf(gi_.y) * tanhx(gg_.y);\
        cb_[2 * p_] = c0v_; cb_[2 * p_ + 1] = c1v_;                             \
        hb_[2 * p_]     = sigf(go_.x) * tanhx(c0v_);                            \
        hb_[2 * p_ + 1] = sigf(go_.y) * tanhx(c1v_);                            \
    }                                                                           \
    *(float4*)&(CS)[srow]     = *(float4*)&cb_[0];                              \
    *(float4*)&(CS)[srow + 4] = *(float4*)&cb_[4];                              \
    *(float4*)&(HS)[srow]     = *(float4*)&hb_[0];                              \
    *(float4*)&(HS)[srow + 4] = *(float4*)&hb_[4];                              \
}

// ---------------- main persistent-per-batch-tile kernel ----------------
__global__ void __launch_bounds__(NTHREADS, 1)
lstm_kernel(const float* __restrict__ x,
            const float* __restrict__ headW, const float* __restrict__ headb,
            const float* __restrict__ confW, const float* __restrict__ confb,
            float* __restrict__ out)
{
    extern __shared__ float sm[];
    float* h0s = sm;                       // [H_][ST]
    float* h1s = h0s + H_ * ST;
    float* c0s = h1s + H_ * ST;
    float* c1s = c0s + H_ * ST;
    float* xsa = c1s + H_ * ST;            // [T_][IN_][ST]
    float* prs = xsa + T_ * IN_ * ST;      // [2][ST]
    float* cfs = prs + 2 * ST;             // [K_][ROWS]

    const int tid = threadIdx.x;
    const int hu  = tid & (H_ - 1);
    const int rg  = tid >> 8;
    const int r0  = rg * 8;
    const int u4  = hu << 2;
    const int u8  = hu << 3;
    const int b0  = blockIdx.x * ROWS;
    const int srow = hu * ST + r0;

    for (int i = tid; i < 4 * H_ * ST; i += NTHREADS) sm[i] = 0.f;
    // preload full x tile for this CTA (one-time)
    for (int i = tid; i < T_ * IN_ * ROWS; i += NTHREADS) {
        int t = i / (IN_ * ROWS);
        int rem = i - t * (IN_ * ROWS);
        int j = rem >> 5, r = rem & (ROWS - 1);
        xsa[t * IN_ * ST + j * ST + r] = x[((size_t)(b0 + r) * T_ + t) * IN_ + j];
    }
    __syncthreads();

    ull acc[4][4];

    // ================= ENCODER =================
    for (int t = 0; t < T_; ++t) {
        // cell 0
        ACC_INIT(g_B0);
        GATE_SEG(xsa + t * IN_ * ST, IN_, g_WT_ih0);
        GATE_SEG(h0s, H_, g_WT_hh0);
        __syncthreads();
        ELEMWISE(c0s, h0s);
        __syncthreads();
        // cell 1
        ACC_INIT(g_B1);
        GATE_SEG(h0s, H_, g_WT_cat1);
        GATE_SEG(h1s, H_, g_WT_cat1 + H_ * G8_);
        __syncthreads();
        ELEMWISE(c1s, h1s);
        __syncthreads();
    }

    // checkpoint encoder state
    {
        int go = hu * B_ + b0 + r0;
        *(float4*)&g_h0e[go]     = *(const float4*)&h0s[srow];
        *(float4*)&g_h0e[go + 4] = *(const float4*)&h0s[srow + 4];
        *(float4*)&g_h1e[go]     = *(const float4*)&h1s[srow];
        *(float4*)&g_h1e[go + 4] = *(const float4*)&h1s[srow + 4];
        *(float4*)&g_c0e[go]     = *(const float4*)&c0s[srow];
        *(float4*)&g_c0e[go + 4] = *(const float4*)&c0s[srow + 4];
        *(float4*)&g_c1e[go]     = *(const float4*)&c1s[srow];
        *(float4*)&g_c1e[go + 4] = *(const float4*)&c1s[srow + 4];
    }

    // confidence head
    if (tid < K_ * ROWS) {
        int k = tid >> 5, r = tid & 31;
        const float* cw = confW + k * H_;
        float s = confb[k];
#pragma unroll 4
        for (int j = 0; j < H_; ++j) s += h1s[j * ST + r] * cw[j];
        cfs[k * ROWS + r] = s;
    }
    __syncthreads();
    if (tid < ROWS) {
        float l0 = cfs[tid], l1 = cfs[ROWS + tid], l2 = cfs[2 * ROWS + tid];
        float m = fmaxf(l0, fmaxf(l1, l2));
        float e0 = __expf(l0 - m), e1 = __expf(l1 - m), e2 = __expf(l2 - m);
        float inv = 1.f / (e0 + e1 + e2);
        float* co = out + (size_t)B_ * K_ * FS_ * 2 + (size_t)(b0 + tid) * K_;
        co[0] = e0 * inv; co[1] = e1 * inv; co[2] = e2 * inv;
    }

    // ================= DECODER (K modes) =================
    for (int k = 0; k < K_; ++k) {
        __syncthreads();
        {   // restore encoder state
            int go = hu * B_ + b0 + r0;
            *(float4*)&h0s[srow]     = *(const float4*)&g_h0e[go];
            *(float4*)&h0s[srow + 4] = *(const float4*)&g_h0e[go + 4];
            *(float4*)&h1s[srow]     = *(const float4*)&g_h1e[go];
            *(float4*)&h1s[srow + 4] = *(const float4*)&g_h1e[go + 4];
            *(float4*)&c0s[srow]     = *(const float4*)&g_c0e[go];
            *(float4*)&c0s[srow + 4] = *(const float4*)&g_c0e[go + 4];
            *(float4*)&c1s[srow]     = *(const float4*)&g_c1e[go];
            *(float4*)&c1s[srow + 4] = *(const float4*)&g_c1e[go + 4];
        }
        if (tid < 2 * ROWS) {   // dec_input = x[:, -1, :2]
            int o = tid & 1, r = tid >> 1;
            prs[o * ST + r] = xsa[(T_ - 1) * IN_ * ST + o * ST + r];
        }
        __syncthreads();

        const float* WDi = g_dWT_ih0[k];
        const float* WD0 = g_dWT_hh0[k];
        const float* WD1 = g_dWT_cat1[k];

        for (int s5 = 0; s5 < FS_; ++s5) {
            ACC_INIT(g_dB0[k]);
            GATE_SEG(prs, 2, WDi);
            GATE_SEG(h0s, H_, WD0);
            __syncthreads();
            ELEMWISE(c0s, h0s);
            __syncthreads();
            ACC_INIT(g_dB1[k]);
            GATE_SEG(h0s, H_, WD1);
            GATE_SEG(h1s, H_, WD1 + H_ * G8_);
            __syncthreads();
            ELEMWISE(c1s, h1s);
            __syncthreads();
            // head: 64 outputs (o,r), 16 threads each + shfl tree
            {
                int outid = tid >> 4;          // 0..63
                int lane16 = tid & 15;
                int o = outid & 1, r = outid >> 1;
                const float* hw = headW + (k * 2 + o) * H_;
                float p = 0.f;
#pragma unroll 4
                for (int j = lane16; j < H_; j += 16) p += h1s[j * ST + r] * hw[j];
                p += __shfl_down_sync(0xffffffffu, p, 8);
                p += __shfl_down_sync(0xffffffffu, p, 4);
                p += __shfl_down_sync(0xffffffffu, p, 2);
                p += __shfl_down_sync(0xffffffffu, p, 1);
                if (lane16 == 0) {
                    float pv = p + headb[k * 2 + o];
                    prs[o * ST + r] = pv;
                    out[(((size_t)(b0 + r) * K_ + k) * FS_ + s5) * 2 + o] = pv;
                }
            }
            __syncthreads();
        }
    }
}

// ---------------- launch ----------------
static const int SMEM_BYTES =
    (4 * H_ * ST + T_ * IN_ * ST + 2 * ST + K_ * ROWS) * (int)sizeof(float);

extern "C" void kernel_launch(void* const* d_in, const int* in_sizes, int n_in,
                              void* d_out, int out_size) {
    const float* x      = (const float*)d_in[0];
    const float* eWih0  = (const float*)d_in[1];
    const float* eWhh0  = (const float*)d_in[2];
    const float* ebih0  = (const float*)d_in[3];
    const float* ebhh0  = (const float*)d_in[4];
    const float* eWih1  = (const float*)d_in[5];
    const float* eWhh1  = (const float*)d_in[6];
    const float* ebih1  = (const float*)d_in[7];
    const float* ebhh1  = (const float*)d_in[8];
    const float* dWih0  = (const float*)d_in[9];
    const float* dWhh0  = (const float*)d_in[10];
    const float* dbih0  = (const float*)d_in[11];
    const float* dbhh0  = (const float*)d_in[12];
    const float* dWih1  = (const float*)d_in[13];
    const float* dWhh1  = (const float*)d_in[14];
    const float* dbih1  = (const float*)d_in[15];
    const float* dbhh1  = (const float*)d_in[16];
    const float* headW  = (const float*)d_in[17];
    const float* headb  = (const float*)d_in[18];
    const float* confW  = (const float*)d_in[19];
    const float* confb  = (const float*)d_in[20];

    cudaFuncSetAttribute(lstm_kernel,
                         cudaFuncAttributeMaxDynamicSharedMemorySize, SMEM_BYTES);

    prep_kernel<<<2048, 512>>>(eWih0, eWhh0, ebih0, ebhh0,
                               eWih1, eWhh1, ebih1, ebhh1,
                               dWih0, dWhh0, dbih0, dbhh0,
                               dWih1, dWhh1, dbih1, dbhh1);
    lstm_kernel<<<NCTA, NTHREADS, SMEM_BYTES>>>(x, headW, headb, confW, confb,
                                                (float*)d_out);
}

// round 3
// speedup vs baseline: 2.5314x; 2.5314x over previous
#include <cuda_runtime.h>
#include <cstddef>

#define B_   4096
#define T_   50
#define IN_  4
#define H_   256
#define G4_  1024
#define K_   3
#define FS_  6
#define ROWS 32
#define RPT  16            // rows per thread
#define ST   36            // padded smem row stride (floats)
#define NTHREADS 512
#define NCTA (B_ / ROWS)   // 128

typedef unsigned long long ull;

// ---------------- device scratch (no allocs allowed) ----------------
// Transposed gate-interleaved weights: WT[j][hu*4 + gate] = W[gate*H+hu][j].
// One pad row at the end so the j+1 software prefetch never goes OOB.
__device__ float g_WT_ih0[(IN_ + 1) * G4_];
__device__ float g_WT_hh0[(H_ + 1) * G4_];
__device__ float g_WT_cat1[(2 * H_ + 1) * G4_];      // [Wih1 ; Whh1]
__device__ float g_B0[G4_];
__device__ float g_B1[G4_];
__device__ float g_dWT_ih0[K_][(2 + 1) * G4_];
__device__ float g_dWT_hh0[K_][(H_ + 1) * G4_];
__device__ float g_dWT_cat1[K_][(2 * H_ + 1) * G4_];
__device__ float g_dB0[K_][G4_];
__device__ float g_dB1[K_][G4_];
// encoder-final state checkpoint, layout [hu*B_ + b]
__device__ float g_h0e[H_ * B_];
__device__ float g_h1e[H_ * B_];
__device__ float g_c0e[H_ * B_];
__device__ float g_c1e[H_ * B_];

// ---------------- packed fp32x2 helpers ----------------
__device__ __forceinline__ void fma2(ull& acc, ull a, ull b) {
    asm("fma.rn.f32x2 %0, %1, %2, %0;" : "+l"(acc) : "l"(a), "l"(b));
}
__device__ __forceinline__ ull pack2(float x, float y) {
    ull u;
    asm("mov.b64 %0, {%1, %2};" : "=l"(u) : "f"(x), "f"(y));
    return u;
}
__device__ __forceinline__ float2 unpack2(ull u) {
    float2 v;
    asm("mov.b64 {%0, %1}, %2;" : "=f"(v.x), "=f"(v.y) : "l"(u));
    return v;
}
__device__ __forceinline__ float sigf(float x)  { return 1.f / (1.f + __expf(-x)); }
__device__ __forceinline__ float tanhx(float x) { return 2.f / (1.f + __expf(-2.f * x)) - 1.f; }

// ---------------- prep: transpose + gate-interleave ----------------
__global__ void prep_kernel(
    const float* __restrict__ eWih0, const float* __restrict__ eWhh0,
    const float* __restrict__ ebih0, const float* __restrict__ ebhh0,
    const float* __restrict__ eWih1, const float* __restrict__ eWhh1,
    const float* __restrict__ ebih1, const float* __restrict__ ebhh1,
    const float* __restrict__ dWih0, const float* __restrict__ dWhh0,
    const float* __restrict__ dbih0, const float* __restrict__ dbhh0,
    const float* __restrict__ dWih1, const float* __restrict__ dWhh1,
    const float* __restrict__ dbih1, const float* __restrict__ dbhh1)
{
    const int N0 = IN_ * G4_;
    const int N1 = H_ * G4_;
    const int N2 = 2 * H_ * G4_;
    const int N3 = G4_, N4 = G4_;
    const int N5 = K_ * 2 * G4_;
    const int N6 = K_ * H_ * G4_;
    const int N7 = K_ * 2 * H_ * G4_;
    const int N8 = K_ * G4_, N9 = K_ * G4_;
    const int TOT = N0 + N1 + N2 + N3 + N4 + N5 + N6 + N7 + N8 + N9;
    for (int idx = blockIdx.x * blockDim.x + threadIdx.x; idx < TOT;
         idx += gridDim.x * blockDim.x) {
        int i = idx;
        if (i < N0) { int j = i / G4_; int u4i = i - j * G4_; int hu = u4i >> 2, g = u4i & 3;
            g_WT_ih0[i] = eWih0[(g * H_ + hu) * IN_ + j]; continue; }
        i -= N0;
        if (i < N1) { int j = i / G4_; int u4i = i - j * G4_; int hu = u4i >> 2, g = u4i & 3;
            g_WT_hh0[i] = eWhh0[(g * H_ + hu) * H_ + j]; continue; }
        i -= N1;
        if (i < N2) { int j = i / G4_; int u4i = i - j * G4_; int hu = u4i >> 2, g = u4i & 3;
            g_WT_cat1[i] = (j < H_) ? eWih1[(g * H_ + hu) * H_ + j]
                                    : eWhh1[(g * H_ + hu) * H_ + (j - H_)]; continue; }
        i -= N2;
        if (i < N3) { int hu = i >> 2, g = i & 3;
            g_B0[i] = ebih0[g * H_ + hu] + ebhh0[g * H_ + hu]; continue; }
        i -= N3;
        if (i < N4) { int hu = i >> 2, g = i & 3;
            g_B1[i] = ebih1[g * H_ + hu] + ebhh1[g * H_ + hu]; continue; }
        i -= N4;
        if (i < N5) { int k = i / (2 * G4_); int rem = i - k * 2 * G4_;
            int j = rem / G4_; int u4i = rem - j * G4_; int hu = u4i >> 2, g = u4i & 3;
            g_dWT_ih0[k][rem] = dWih0[(k * G4_ + g * H_ + hu) * 2 + j]; continue; }
        i -= N5;
        if (i < N6) { int k = i / (H_ * G4_); int rem = i - k * H_ * G4_;
            int j = rem / G4_; int u4i = rem - j * G4_; int hu = u4i >> 2, g = u4i & 3;
            g_dWT_hh0[k][rem] = dWhh0[(k * G4_ + g * H_ + hu) * H_ + j]; continue; }
        i -= N6;
        if (i < N7) { int k = i / (2 * H_ * G4_); int rem = i - k * 2 * H_ * G4_;
            int j = rem / G4_; int u4i = rem - j * G4_; int hu = u4i >> 2, g = u4i & 3;
            g_dWT_cat1[k][rem] = (j < H_) ? dWih1[(k * G4_ + g * H_ + hu) * H_ + j]
                                          : dWhh1[(k * G4_ + g * H_ + hu) * H_ + (j - H_)]; continue; }
        i -= N7;
        if (i < N8) { int k = i / G4_; int rem = i - k * G4_; int hu = rem >> 2, g = rem & 3;
            g_dB0[k][rem] = dbih0[k * G4_ + g * H_ + hu] + dbhh0[k * G4_ + g * H_ + hu]; continue; }
        i -= N8;
        { int k = i / G4_; int rem = i - k * G4_; int hu = rem >> 2, g = rem & 3;
            g_dB1[k][rem] = dbih1[k * G4_ + g * H_ + hu] + dbhh1[k * G4_ + g * H_ + hu]; }
    }
}

// ---------------- hot-loop macros ----------------
// acc[p][g]: f32x2 accumulator, row pair (r0+2p, r0+2p+1), gate g; p=0..7 (16 rows)
#define ACC_INIT(BIAS) {                                                        \
    float4 bv_ = *(const float4*)((BIAS) + u4);                                 \
    ull b0_ = pack2(bv_.x, bv_.x), b1_ = pack2(bv_.y, bv_.y);                   \
    ull b2_ = pack2(bv_.z, bv_.z), b3_ = pack2(bv_.w, bv_.w);                   \
    _Pragma("unroll")                                                           \
    for (int p_ = 0; p_ < 8; ++p_) {                                            \
        acc[p_][0] = b0_; acc[p_][1] = b1_; acc[p_][2] = b2_; acc[p_][3] = b3_; \
    } }

// 1 LDG.128 (16B) feeds 32 FFMA2; next j's weights prefetched (pad row covers tail)
#define GATE_SEG(SRC, NJ, WT) {                                                 \
    const float* __restrict__ wt_ = (WT);                                       \
    const float* __restrict__ sr_ = (SRC) + r0;                                 \
    float4 wc_ = *(const float4*)(wt_ + u4);                                    \
    _Pragma("unroll 2")                                                         \
    for (int j = 0; j < (NJ); ++j) {                                            \
        float4 wn_ = *(const float4*)(wt_ + (j + 1) * G4_ + u4);                \
        const ull* hp_ = (const ull*)(sr_ + j * ST);                            \
        ull h_[8];                                                              \
        _Pragma("unroll")                                                       \
        for (int p_ = 0; p_ < 8; ++p_) h_[p_] = hp_[p_];                        \
        ull wi_ = pack2(wc_.x, wc_.x), wf_ = pack2(wc_.y, wc_.y);               \
        ull wg_ = pack2(wc_.z, wc_.z), wo_ = pack2(wc_.w, wc_.w);               \
        _Pragma("unroll")                                                       \
        for (int p_ = 0; p_ < 8; ++p_) {                                        \
            fma2(acc[p_][0], h_[p_], wi_);                                      \
            fma2(acc[p_][1], h_[p_], wf_);                                      \
            fma2(acc[p_][2], h_[p_], wg_);                                      \
            fma2(acc[p_][3], h_[p_], wo_);                                      \
        }                                                                       \
        wc_ = wn_;                                                              \
    } }

// reads c from CS (same-thread), writes new c to CS and new h to HD (double buffer)
#define ELEMWISE(CS, HD) {                                                      \
    float cb_[16], hb_[16];                                                     \
    _Pragma("unroll")                                                           \
    for (int q_ = 0; q_ < 4; ++q_)                                              \
        *(float4*)&cb_[4 * q_] = *(const float4*)&(CS)[srow + 4 * q_];          \
    _Pragma("unroll")                                                           \
    for (int p_ = 0; p_ < 8; ++p_) {                                            \
        float2 gi_ = unpack2(acc[p_][0]);                                       \
        float2 gf_ = unpack2(acc[p_][1]);                                       \
        float2 gg_ = unpack2(acc[p_][2]);                                       \
        float2 go_ = unpack2(acc[p_][3]);                                       \
        float ca_ = sigf(gf_.x) * cb_[2 * p_]     + sigf(gi_.x) * tanhx(gg_.x); \
        float cx_ = sigf(gf_.y) * cb_[2 * p_ + 1] + sigf(gi_.y) * tanhx(gg_.y); \
        cb_[2 * p_] = ca_; cb_[2 * p_ + 1] = cx_;                               \
        hb_[2 * p_]     = sigf(go_.x) * tanhx(ca_);                             \
        hb_[2 * p_ + 1] = sigf(go_.y) * tanhx(cx_);                             \
    }                                                                           \
    _Pragma("unroll")                                                           \
    for (int q_ = 0; q_ < 4; ++q_) {                                            \
        *(float4*)&(CS)[srow + 4 * q_] = *(float4*)&cb_[4 * q_];                \
        *(float4*)&(HD)[srow + 4 * q_] = *(float4*)&hb_[4 * q_];                \
    } }

// ---------------- main persistent-per-batch-tile kernel ----------------
__global__ void __launch_bounds__(NTHREADS, 1)
lstm_kernel(const float* __restrict__ x,
            const float* __restrict__ headW, const float* __restrict__ headb,
            const float* __restrict__ confW, const float* __restrict__ confb,
            float* __restrict__ out)
{
    extern __shared__ float sm[];
    float* h0a = sm;                       // [H_][ST] x2 (double buffer)
    float* h0b = h0a + H_ * ST;
    float* h1a = h0b + H_ * ST;
    float* h1b = h1a + H_ * ST;
    float* c0s = h1b + H_ * ST;
    float* c1s = c0s + H_ * ST;
    float* xs  = c1s + H_ * ST;            // [2][IN_][ST]
    float* prs = xs + 2 * IN_ * ST;        // [2][ST]
    float* cfs = prs + 2 * ST;             // [K_][ROWS]

    const int tid = threadIdx.x;
    const int hu  = tid & (H_ - 1);
    const int rg  = tid >> 8;              // 0 or 1
    const int r0  = rg * RPT;
    const int u4  = hu << 2;
    const int b0  = blockIdx.x * ROWS;
    const int srow = hu * ST + r0;

    // zero the initial read buffers + cell states
    for (int i = tid; i < H_ * ST; i += NTHREADS) {
        h0a[i] = 0.f; h1a[i] = 0.f; c0s[i] = 0.f; c1s[i] = 0.f;
    }
    // stage x[t=0]
    if (tid < IN_ * ROWS) {
        int j = tid & 3, r = tid >> 2;
        xs[j * ST + r] = x[((size_t)(b0 + r) * T_) * IN_ + j];
    }
    __syncthreads();

    ull acc[8][4];
    float *h0r = h0a, *h0w = h0b, *h1r = h1a, *h1w = h1b;

    // ================= ENCODER =================
    for (int t = 0; t < T_; ++t) {
        // stage x[t+1] into the other xs buffer (read at t+1, after end-of-step sync)
        if (t + 1 < T_ && tid < IN_ * ROWS) {
            int j = tid & 3, r = tid >> 2;
            xs[((t + 1) & 1) * IN_ * ST + j * ST + r] =
                x[((size_t)(b0 + r) * T_ + (t + 1)) * IN_ + j];
        }
        // cell 0: reads xs[t&1], h0r -> writes h0w (no sync needed before ELEMWISE)
        ACC_INIT(g_B0);
        GATE_SEG(xs + (t & 1) * IN_ * ST, IN_, g_WT_ih0);
        GATE_SEG(h0r, H_, g_WT_hh0);
        ELEMWISE(c0s, h0w);
        __syncthreads();
        // cell 1: reads h0w, h1r -> writes h1w
        ACC_INIT(g_B1);
        GATE_SEG(h0w, H_, g_WT_cat1);
        GATE_SEG(h1r, H_, g_WT_cat1 + H_ * G4_);
        ELEMWISE(c1s, h1w);
        __syncthreads();
        { float* tmp = h0r; h0r = h0w; h0w = tmp; }
        { float* tmp = h1r; h1r = h1w; h1w = tmp; }
    }
    // final state now in h0r/h1r (T_ even -> h0a/h1a)

    // checkpoint encoder state
    {
        int go = hu * B_ + b0 + r0;
#pragma unroll
        for (int q = 0; q < 4; ++q) {
            *(float4*)&g_h0e[go + 4 * q] = *(const float4*)&h0r[srow + 4 * q];
            *(float4*)&g_h1e[go + 4 * q] = *(const float4*)&h1r[srow + 4 * q];
            *(float4*)&g_c0e[go + 4 * q] = *(const float4*)&c0s[srow + 4 * q];
            *(float4*)&g_c1e[go + 4 * q] = *(const float4*)&c1s[srow + 4 * q];
        }
    }

    // confidence head (final encoder h1 = h1r)
    if (tid < K_ * ROWS) {
        int k = tid >> 5, r = tid & 31;
        const float* cw = confW + k * H_;
        float s = confb[k];
#pragma unroll 4
        for (int j = 0; j < H_; ++j) s += h1r[j * ST + r] * cw[j];
        cfs[k * ROWS + r] = s;
    }
    __syncthreads();
    if (tid < ROWS) {
        float l0 = cfs[tid], l1 = cfs[ROWS + tid], l2 = cfs[2 * ROWS + tid];
        float m = fmaxf(l0, fmaxf(l1, l2));
        float e0 = __expf(l0 - m), e1 = __expf(l1 - m), e2 = __expf(l2 - m);
        float inv = 1.f / (e0 + e1 + e2);
        float* co = out + (size_t)B_ * K_ * FS_ * 2 + (size_t)(b0 + tid) * K_;
        co[0] = e0 * inv; co[1] = e1 * inv; co[2] = e2 * inv;
    }

    // ================= DECODER (K modes) =================
    for (int k = 0; k < K_; ++k) {
        __syncthreads();
        {   // restore encoder state into the 'a' buffers
            int go = hu * B_ + b0 + r0;
#pragma unroll
            for (int q = 0; q < 4; ++q) {
                *(float4*)&h0a[srow + 4 * q] = *(const float4*)&g_h0e[go + 4 * q];
                *(float4*)&h1a[srow + 4 * q] = *(const float4*)&g_h1e[go + 4 * q];
                *(float4*)&c0s[srow + 4 * q] = *(const float4*)&g_c0e[go + 4 * q];
                *(float4*)&c1s[srow + 4 * q] = *(const float4*)&g_c1e[go + 4 * q];
            }
        }
        if (tid < 2 * ROWS) {   // dec_input = x[:, -1, :2]
            int o = tid & 1, r = tid >> 1;
            prs[o * ST + r] = x[((size_t)(b0 + r) * T_ + (T_ - 1)) * IN_ + o];
        }
        __syncthreads();

        float *d0r = h0a, *d0w = h0b, *d1r = h1a, *d1w = h1b;
        const float* WDi = g_dWT_ih0[k];
        const float* WD0 = g_dWT_hh0[k];
        const float* WD1 = g_dWT_cat1[k];

        for (int s5 = 0; s5 < FS_; ++s5) {
            ACC_INIT(g_dB0[k]);
            GATE_SEG(prs, 2, WDi);
            GATE_SEG(d0r, H_, WD0);
            ELEMWISE(c0s, d0w);
            __syncthreads();
            ACC_INIT(g_dB1[k]);
            GATE_SEG(d0w, H_, WD1);
            GATE_SEG(d1r, H_, WD1 + H_ * G4_);
            ELEMWISE(c1s, d1w);
            __syncthreads();
            // head: 64 outputs (o,r), 8 threads each + shfl tree; reads d1w
            {
                int outid = tid >> 3;          // 0..63
                int lane8 = tid & 7;
                int o = outid & 1, r = outid >> 1;
                const float* hw = headW + (k * 2 + o) * H_;
                float p = 0.f;
#pragma unroll 4
                for (int j = lane8; j < H_; j += 8) p += d1w[j * ST + r] * hw[j];
                p += __shfl_down_sync(0xffffffffu, p, 4);
                p += __shfl_down_sync(0xffffffffu, p, 2);
                p += __shfl_down_sync(0xffffffffu, p, 1);
                if (lane8 == 0) {
                    float pv = p + headb[k * 2 + o];
                    prs[o * ST + r] = pv;
                    out[(((size_t)(b0 + r) * K_ + k) * FS_ + s5) * 2 + o] = pv;
                }
            }
            __syncthreads();
            { float* tmp = d0r; d0r = d0w; d0w = tmp; }
            { float* tmp = d1r; d1r = d1w; d1w = tmp; }
        }
    }
}

// ---------------- launch ----------------
static const int SMEM_BYTES =
    (6 * H_ * ST + 2 * IN_ * ST + 2 * ST + K_ * ROWS) * (int)sizeof(float);

extern "C" void kernel_launch(void* const* d_in, const int* in_sizes, int n_in,
                              void* d_out, int out_size) {
    const float* x      = (const float*)d_in[0];
    const float* eWih0  = (const float*)d_in[1];
    const float* eWhh0  = (const float*)d_in[2];
    const float* ebih0  = (const float*)d_in[3];
    const float* ebhh0  = (const float*)d_in[4];
    const float* eWih1  = (const float*)d_in[5];
    const float* eWhh1  = (const float*)d_in[6];
    const float* ebih1  = (const float*)d_in[7];
    const float* ebhh1  = (const float*)d_in[8];
    const float* dWih0  = (const float*)d_in[9];
    const float* dWhh0  = (const float*)d_in[10];
    const float* dbih0  = (const float*)d_in[11];
    const float* dbhh0  = (const float*)d_in[12];
    const float* dWih1  = (const float*)d_in[13];
    const float* dWhh1  = (const float*)d_in[14];
    const float* dbih1  = (const float*)d_in[15];
    const float* dbhh1  = (const float*)d_in[16];
    const float* headW  = (const float*)d_in[17];
    const float* headb  = (const float*)d_in[18];
    const float* confW  = (const float*)d_in[19];
    const float* confb  = (const float*)d_in[20];

    cudaFuncSetAttribute(lstm_kernel,
                         cudaFuncAttributeMaxDynamicSharedMemorySize, SMEM_BYTES);

    prep_kernel<<<2048, 512>>>(eWih0, eWhh0, ebih0, ebhh0,
                               eWih1, eWhh1, ebih1, ebhh1,
                               dWih0, dWhh0, dbih0, dbhh0,
                               dWih1, dWhh1, dbih1, dbhh1);
    lstm_kernel<<<NCTA, NTHREADS, SMEM_BYTES>>>(x, headW, headb, confW, confb,
                                                (float*)d_out);
}